// round 5
// baseline (speedup 1.0000x reference)
#include <cuda_runtime.h>
#include <cuda_bf16.h>
#include <cstdint>

#define D 64
#define MAX_TOKENS 4096

// Scratch (no cudaMalloc allowed)
__device__ __align__(16) __nv_bfloat16 g_hi[MAX_TOKENS * D];
__device__ __align__(16) __nv_bfloat16 g_lo[MAX_TOKENS * D];
__device__ float g_x2[MAX_TOKENS];
__device__ float g_rinv[MAX_TOKENS];

// ---------------------------------------------------------------------------
// helpers
// ---------------------------------------------------------------------------
__device__ __forceinline__ uint32_t smem_u32(const void* p) {
    uint32_t a;
    asm("{ .reg .u64 t; cvta.to.shared.u64 t, %1; cvt.u32.u64 %0, t; }"
        : "=r"(a) : "l"(p));
    return a;
}
__device__ __forceinline__ void ldsm_x4(uint32_t& r0, uint32_t& r1,
                                        uint32_t& r2, uint32_t& r3,
                                        uint32_t addr) {
    asm volatile("ldmatrix.sync.aligned.m8n8.x4.shared.b16 {%0,%1,%2,%3}, [%4];"
                 : "=r"(r0), "=r"(r1), "=r"(r2), "=r"(r3) : "r"(addr));
}
__device__ __forceinline__ void ldsm_x2(uint32_t& r0, uint32_t& r1,
                                        uint32_t addr) {
    asm volatile("ldmatrix.sync.aligned.m8n8.x2.shared.b16 {%0,%1}, [%2];"
                 : "=r"(r0), "=r"(r1) : "r"(addr));
}
__device__ __forceinline__ void mma16816(float* d, const uint32_t* a,
                                         const uint32_t* b) {
    asm volatile(
        "mma.sync.aligned.m16n8k16.row.col.f32.bf16.bf16.f32 "
        "{%0,%1,%2,%3}, {%4,%5,%6,%7}, {%8,%9}, {%0,%1,%2,%3};"
        : "+f"(d[0]), "+f"(d[1]), "+f"(d[2]), "+f"(d[3])
        : "r"(a[0]), "r"(a[1]), "r"(a[2]), "r"(a[3]), "r"(b[0]), "r"(b[1]));
}

// ---------------------------------------------------------------------------
// Prep: id-dtype detect, gather, project, x2, 1/(1-x2), bf16 hi/lo split.
// One warp per token.
// ---------------------------------------------------------------------------
__global__ __launch_bounds__(256)
void prep_kernel(const void* __restrict__ ids_raw,
                 const float* __restrict__ W,
                 int n_ids, int num_tok) {
    const int* w32 = (const int*)ids_raw;
    int any = 0;
    for (int i = threadIdx.x * 2 + 1; i < n_ids; i += 2 * blockDim.x)
        any |= w32[i];
    int is64 = (__syncthreads_or(any) == 0);

    int warp = (blockIdx.x * blockDim.x + threadIdx.x) >> 5;
    int lane = threadIdx.x & 31;
    if (warp >= n_ids) return;

    long long id = is64 ? ((const long long*)ids_raw)[warp]
                        : (long long)w32[warp];
    if (id < 0) id = 0;
    if (id > (long long)(num_tok - 1)) id = num_tok - 1;

    const float* row = W + (size_t)id * D;
    float v0 = row[lane];
    float v1 = row[lane + 32];
    float s = v0 * v0 + v1 * v1;
#pragma unroll
    for (int o = 16; o; o >>= 1) s += __shfl_xor_sync(0xffffffffu, s, o);

    const float max_norm = 1.0f - 1e-5f;
    float norm = sqrtf(s);
    float f = (norm > max_norm) ? (max_norm / fmaxf(norm, 1e-12f)) : 1.0f;
    v0 *= f; v1 *= f;

    __nv_bfloat16 h0 = __float2bfloat16_rn(v0);
    __nv_bfloat16 h1 = __float2bfloat16_rn(v1);
    g_hi[warp * D + lane]      = h0;
    g_hi[warp * D + lane + 32] = h1;
    g_lo[warp * D + lane]      = __float2bfloat16_rn(v0 - __bfloat162float(h0));
    g_lo[warp * D + lane + 32] = __float2bfloat16_rn(v1 - __bfloat162float(h1));

    float s2 = v0 * v0 + v1 * v1;
#pragma unroll
    for (int o = 16; o; o >>= 1) s2 += __shfl_xor_sync(0xffffffffu, s2, o);

    if (lane == 0) {
        g_x2[warp]   = s2;
        g_rinv[warp] = 1.0f / (1.0f - s2);
    }
}

// ---------------------------------------------------------------------------
// Epilogue element. nscln2 = -scale * ln(2); rj2 = 2 * rinv_j.
// ---------------------------------------------------------------------------
__device__ __forceinline__ float bias_elt(float xi, float ri, float xjv,
                                          float rj2, float g, float nscln2) {
    float sq  = fmaxf(fmaf(-2.0f, g, xi + xjv), 0.0f);
    float x   = (sq * ri) * rj2;
    float xq  = (1.0f + x) - 1.0f;              // reference fp32 quantization
    float xe  = fmaxf(xq, 1.1920929e-7f);       // reference clamp (1+1e-7 -> 1+ulp)
    float prod = fmaf(xe, xe, xe + xe);         // xe*(xe+2)
    float s;
    asm("sqrt.approx.f32 %0, %1;" : "=f"(s) : "f"(prod));
    float y = 1.0f + (xe + s);
    float l;
    asm("lg2.approx.f32 %0, %1;" : "=f"(l) : "f"(y));
    return nscln2 * l;                           // -sc * ln(y)
}

// ---------------------------------------------------------------------------
// Main: upper-triangle 128x128 tiles via mma.sync bf16 (hi/lo split).
// Off-diagonal tiles mirror their result through a smem transpose so both
// (i,j) and (j,i) blocks are written with coalesced stores.
// ---------------------------------------------------------------------------
#define LDB     144                     // bytes per smem bf16 tile row
#define T_AH    0                       // i-block hi
#define T_AL    (128 * LDB)             // i-block lo
#define T_BH    (2 * 128 * LDB)         // j-block hi
#define T_BL    (3 * 128 * LDB)         // j-block lo
#define O_X2I   (4 * 128 * LDB)
#define O_RI    (O_X2I + 512)
#define O_X2J   (O_RI + 512)
#define O_RJ    (O_X2J + 512)
#define SMEM_TOT (O_RJ + 512)           // 75776 bytes
#define PSTAG   132                     // f32 staging pitch (floats)

__global__ __launch_bounds__(256, 2)
void bias_kernel(const float* __restrict__ scale_p,
                 float* __restrict__ out, int S) {
    extern __shared__ char sm[];
    uint32_t sb = smem_u32(sm);

    // decode (ti, tj) upper-triangle pair from blockIdx.x
    int ntile = S >> 7;
    int idx = blockIdx.x;
    int ti = 0, row = ntile;
    while (idx >= row) { idx -= row; row--; ti++; }
    int tj = ti + idx;
    bool mirror = (ti != tj);

    int b  = blockIdx.z;
    int i0 = ti * 128;
    int j0 = tj * 128;
    int base = b * S;
    int t = threadIdx.x;
    int wid = t >> 5, lane = t & 31;

    // ---- stage tiles: 128 rows x 64 bf16 (128B) -> smem pitch 144B ----
    {
        const __nv_bfloat16* srcs[4] = {
            g_hi + (size_t)(base + i0) * D, g_lo + (size_t)(base + i0) * D,
            g_hi + (size_t)(base + j0) * D, g_lo + (size_t)(base + j0) * D};
        const int offs[4] = {T_AH, T_AL, T_BH, T_BL};
#pragma unroll
        for (int m = 0; m < 4; m++) {
            const uint4* src = (const uint4*)srcs[m];
#pragma unroll
            for (int it = 0; it < 4; it++) {
                int idx2 = t + it * 256;        // 0..1023
                int row2 = idx2 >> 3, ch = idx2 & 7;
                uint4 v = src[row2 * 8 + ch];
                *(uint4*)(sm + offs[m] + row2 * LDB + ch * 16) = v;
            }
        }
        if (t < 128) {
            ((float*)(sm + O_X2I))[t] = g_x2[base + i0 + t];
            ((float*)(sm + O_RI))[t]  = g_rinv[base + i0 + t];
        } else {
            int u = t - 128;
            ((float*)(sm + O_X2J))[u] = g_x2[base + j0 + u];
            ((float*)(sm + O_RJ))[u]  = g_rinv[base + j0 + u];
        }
    }
    __syncthreads();

    int wm = wid >> 2;          // 0..1  (m block of 64)
    int wn = wid & 3;           // 0..3  (n block of 32)

    float acc[4][4][4];
#pragma unroll
    for (int mt = 0; mt < 4; mt++)
#pragma unroll
        for (int nt = 0; nt < 4; nt++)
#pragma unroll
            for (int r = 0; r < 4; r++) acc[mt][nt][r] = 0.0f;

    int lm = lane >> 3, lr = lane & 7;
    int a_row = wm * 64 + (lm & 1) * 8 + lr;
    int a_kb  = (lm >> 1) * 16;
    int bl = lane & 15;
    int b_row = wn * 32 + (bl & 7);
    int b_kb  = (bl >> 3) * 16;

    const int passA[3] = {T_AH, T_AH, T_AL};
    const int passB[3] = {T_BH, T_BL, T_BH};

#pragma unroll
    for (int p = 0; p < 3; p++) {
        uint32_t aBase = sb + passA[p] + a_row * LDB + a_kb;
        uint32_t bBase = sb + passB[p] + b_row * LDB + b_kb;
#pragma unroll
        for (int ks = 0; ks < 4; ks++) {
            uint32_t a[4][4], bf[4][2];
#pragma unroll
            for (int mt = 0; mt < 4; mt++)
                ldsm_x4(a[mt][0], a[mt][1], a[mt][2], a[mt][3],
                        aBase + mt * 16 * LDB + ks * 32);
#pragma unroll
            for (int nt = 0; nt < 4; nt++)
                ldsm_x2(bf[nt][0], bf[nt][1],
                        bBase + nt * 8 * LDB + ks * 32);
#pragma unroll
            for (int mt = 0; mt < 4; mt++)
#pragma unroll
                for (int nt = 0; nt < 4; nt++)
                    mma16816(acc[mt][nt], a[mt], bf[nt]);
        }
    }

    // All ldsm reads of the tile region done; staging may overwrite it.
    __syncthreads();

    // ---- epilogue ----
    float sc = scale_p[0];
    float nscln2 = -sc * 0.6931471805599453f;
    int g  = lane >> 2;          // 0..7
    int tq = lane & 3;           // 0..3
    const float* sx2i = (const float*)(sm + O_X2I);
    const float* sri  = (const float*)(sm + O_RI);
    const float* sx2j = (const float*)(sm + O_X2J);
    const float* srj  = (const float*)(sm + O_RJ);
    float* stag = (float*)sm;    // [j][i], pitch PSTAG floats (overlays tiles)

#pragma unroll
    for (int mt = 0; mt < 4; mt++) {
        int i_a = wm * 64 + mt * 16 + g;
        int i_b = i_a + 8;
        float xia = sx2i[i_a], ria = sri[i_a];
        float xib = sx2i[i_b], rib = sri[i_b];
        size_t rowA = (size_t)b * S * S + (size_t)(i0 + i_a) * S + j0;
        size_t rowB = rowA + 8u * S;
#pragma unroll
        for (int nt = 0; nt < 4; nt++) {
            int j_c = wn * 32 + nt * 8 + 2 * tq;
            float xj0 = sx2j[j_c],     rj20 = srj[j_c] * 2.0f;
            float xj1 = sx2j[j_c + 1], rj21 = srj[j_c + 1] * 2.0f;
            float2 oA, oB;
            oA.x = bias_elt(xia, ria, xj0, rj20, acc[mt][nt][0], nscln2);
            oA.y = bias_elt(xia, ria, xj1, rj21, acc[mt][nt][1], nscln2);
            oB.x = bias_elt(xib, rib, xj0, rj20, acc[mt][nt][2], nscln2);
            oB.y = bias_elt(xib, rib, xj1, rj21, acc[mt][nt][3], nscln2);
            *(float2*)(out + rowA + j_c) = oA;
            *(float2*)(out + rowB + j_c) = oB;
            if (mirror) {
                // transposed staging: stag[j][i] (STS banks 8*tq+g: conflict-free)
                stag[(j_c)     * PSTAG + i_a] = oA.x;
                stag[(j_c + 1) * PSTAG + i_a] = oA.y;
                stag[(j_c)     * PSTAG + i_b] = oB.x;
                stag[(j_c + 1) * PSTAG + i_b] = oB.y;
            }
        }
    }

    // ---- mirror: coalesced store of the transposed tile at (j0, i0) ----
    if (mirror) {
        __syncthreads();
        size_t mbase = (size_t)b * S * S + (size_t)j0 * S + i0;
#pragma unroll
        for (int r = 0; r < 16; r++) {
            int j = r * 8 + wid;                    // 128 rows over 8 warps
            float4 v = *(const float4*)(stag + j * PSTAG + 4 * lane);
            *(float4*)(out + mbase + (size_t)j * S + 4 * lane) = v;
        }
    }
}

// ---------------------------------------------------------------------------
extern "C" void kernel_launch(void* const* d_in, const int* in_sizes, int n_in,
                              void* d_out, int out_size) {
    const void*  ids     = d_in[0];
    const float* W       = (const float*)d_in[1];
    const float* scale_p = (const float*)d_in[2];
    float* out = (float*)d_out;

    int n_ids   = in_sizes[0];            // B*S = 4096
    int num_tok = in_sizes[1] / D;        // 30522
    int S       = out_size / n_ids;       // 1024
    int B       = n_ids / S;              // 4

    int prep_blocks = (n_ids + 7) / 8;
    prep_kernel<<<prep_blocks, 256>>>(ids, W, n_ids, num_tok);

    static int attr_set = 0;
    if (!attr_set) {
        cudaFuncSetAttribute(bias_kernel,
                             cudaFuncAttributeMaxDynamicSharedMemorySize,
                             SMEM_TOT);
        attr_set = 1;
    }

    int ntile = S / 128;
    int pairs = ntile * (ntile + 1) / 2;  // 36 for S=1024
    dim3 grid(pairs, 1, B);
    bias_kernel<<<grid, 256, SMEM_TOT>>>(scale_p, out, S);
}

// round 6
// speedup vs baseline: 1.2542x; 1.2542x over previous
#include <cuda_runtime.h>
#include <cuda_bf16.h>
#include <cstdint>

#define D 64
#define MAX_TOKENS 4096

// Scratch (no cudaMalloc allowed)
__device__ __align__(16) __nv_bfloat16 g_hi[MAX_TOKENS * D];
__device__ __align__(16) __nv_bfloat16 g_lo[MAX_TOKENS * D];
__device__ float g_P[MAX_TOKENS];   // 2 / (1 - x2)
__device__ float g_U[MAX_TOKENS];   // x2 / (1 - x2)

// ---------------------------------------------------------------------------
// helpers
// ---------------------------------------------------------------------------
__device__ __forceinline__ uint32_t smem_u32(const void* p) {
    uint32_t a;
    asm("{ .reg .u64 t; cvta.to.shared.u64 t, %1; cvt.u32.u64 %0, t; }"
        : "=r"(a) : "l"(p));
    return a;
}
__device__ __forceinline__ void ldsm_x4(uint32_t& r0, uint32_t& r1,
                                        uint32_t& r2, uint32_t& r3,
                                        uint32_t addr) {
    asm volatile("ldmatrix.sync.aligned.m8n8.x4.shared.b16 {%0,%1,%2,%3}, [%4];"
                 : "=r"(r0), "=r"(r1), "=r"(r2), "=r"(r3) : "r"(addr));
}
__device__ __forceinline__ void mma16816(float* d, const uint32_t* a,
                                         const uint32_t* b) {
    asm volatile(
        "mma.sync.aligned.m16n8k16.row.col.f32.bf16.bf16.f32 "
        "{%0,%1,%2,%3}, {%4,%5,%6,%7}, {%8,%9}, {%0,%1,%2,%3};"
        : "+f"(d[0]), "+f"(d[1]), "+f"(d[2]), "+f"(d[3])
        : "r"(a[0]), "r"(a[1]), "r"(a[2]), "r"(a[3]), "r"(b[0]), "r"(b[1]));
}

// ---------------------------------------------------------------------------
// Prep: id-dtype detect, gather, project, P/U, bf16 hi/lo split.
// One warp per token.
// ---------------------------------------------------------------------------
__global__ __launch_bounds__(256)
void prep_kernel(const void* __restrict__ ids_raw,
                 const float* __restrict__ W,
                 int n_ids, int num_tok) {
    const int* w32 = (const int*)ids_raw;
    int any = 0;
    for (int i = threadIdx.x * 2 + 1; i < n_ids; i += 2 * blockDim.x)
        any |= w32[i];
    int is64 = (__syncthreads_or(any) == 0);

    int warp = (blockIdx.x * blockDim.x + threadIdx.x) >> 5;
    int lane = threadIdx.x & 31;
    if (warp >= n_ids) return;

    long long id = is64 ? ((const long long*)ids_raw)[warp]
                        : (long long)w32[warp];
    if (id < 0) id = 0;
    if (id > (long long)(num_tok - 1)) id = num_tok - 1;

    const float* row = W + (size_t)id * D;
    float v0 = row[lane];
    float v1 = row[lane + 32];
    float s = v0 * v0 + v1 * v1;
#pragma unroll
    for (int o = 16; o; o >>= 1) s += __shfl_xor_sync(0xffffffffu, s, o);

    const float max_norm = 1.0f - 1e-5f;
    float norm = sqrtf(s);
    float f = (norm > max_norm) ? (max_norm / fmaxf(norm, 1e-12f)) : 1.0f;
    v0 *= f; v1 *= f;

    __nv_bfloat16 h0 = __float2bfloat16_rn(v0);
    __nv_bfloat16 h1 = __float2bfloat16_rn(v1);
    g_hi[warp * D + lane]      = h0;
    g_hi[warp * D + lane + 32] = h1;
    g_lo[warp * D + lane]      = __float2bfloat16_rn(v0 - __bfloat162float(h0));
    g_lo[warp * D + lane + 32] = __float2bfloat16_rn(v1 - __bfloat162float(h1));

    float s2 = v0 * v0 + v1 * v1;
#pragma unroll
    for (int o = 16; o; o >>= 1) s2 += __shfl_xor_sync(0xffffffffu, s2, o);

    if (lane == 0) {
        float r = 1.0f / (1.0f - s2);
        g_P[warp] = 2.0f * r;
        g_U[warp] = s2 * r;
    }
}

// ---------------------------------------------------------------------------
// Epilogue element: x = Pi*Uj + Pj*Ui - Pi*Pj*g ; dist = acosh(1+x)
// ---------------------------------------------------------------------------
__device__ __forceinline__ float bias_elt(float Pi, float Ui, float Pj,
                                          float Uj, float g, float nscln2) {
    float m  = Pj * Ui;
    float f1 = fmaf(Pi, Uj, m);
    float tt = Pi * Pj;
    float x  = fmaf(-tt, g, f1);
    float xe = fmaxf(x, 1.1920929e-7f);          // matches ref clamp (1+1e-7)
    float pr = fmaf(xe, xe, xe + xe);            // xe*(xe+2)
    float s;
    asm("sqrt.approx.f32 %0, %1;" : "=f"(s) : "f"(pr));
    float y = 1.0f + (xe + s);
    float l;
    asm("lg2.approx.f32 %0, %1;" : "=f"(l) : "f"(y));
    return nscln2 * l;                            // -sc * ln(y)
}

// ---------------------------------------------------------------------------
// Main: upper-triangle 64x64 tiles, 128 threads (4 warps, 2x2), mma.sync bf16
// hi/lo split. Off-diagonal tiles mirrored via smem transpose.
// ---------------------------------------------------------------------------
#define LDB     144                     // bytes per smem bf16 tile row
#define T_AH    0                       // i-block hi
#define T_AL    (64 * LDB)              // i-block lo
#define T_BH    (2 * 64 * LDB)          // j-block hi
#define T_BL    (3 * 64 * LDB)          // j-block lo
#define O_PI    (4 * 64 * LDB)
#define O_UI    (O_PI + 256)
#define O_PJ    (O_UI + 256)
#define O_UJ    (O_PJ + 256)
#define SMEM_TOT (O_UJ + 256)           // 37888 bytes
#define PSTAG   68                      // f32 staging pitch (floats)

__global__ __launch_bounds__(128, 4)
void bias_kernel(const float* __restrict__ scale_p,
                 float* __restrict__ out, int S) {
    extern __shared__ char sm[];
    uint32_t sb = smem_u32(sm);

    // decode (ti, tj) upper-triangle pair from blockIdx.x
    int ntile = S >> 6;
    int idx = blockIdx.x;
    int ti = 0, rowc = ntile;
    while (idx >= rowc) { idx -= rowc; rowc--; ti++; }
    int tj = ti + idx;
    bool mirror = (ti != tj);

    int b  = blockIdx.z;
    int i0 = ti * 64;
    int j0 = tj * 64;
    int base = b * S;
    int t = threadIdx.x;
    int wid = t >> 5, lane = t & 31;

    // ---- stage tiles: 64 rows x 64 bf16 (128B) -> smem pitch 144B ----
    {
        const __nv_bfloat16* srcs[4] = {
            g_hi + (size_t)(base + i0) * D, g_lo + (size_t)(base + i0) * D,
            g_hi + (size_t)(base + j0) * D, g_lo + (size_t)(base + j0) * D};
        const int offs[4] = {T_AH, T_AL, T_BH, T_BL};
#pragma unroll
        for (int m = 0; m < 4; m++) {
            const uint4* src = (const uint4*)srcs[m];
#pragma unroll
            for (int it = 0; it < 4; it++) {
                int idx2 = t + it * 128;        // 0..511
                int row2 = idx2 >> 3, ch = idx2 & 7;
                uint4 v = src[row2 * 8 + ch];
                *(uint4*)(sm + offs[m] + row2 * LDB + ch * 16) = v;
            }
        }
        if (t < 64) {
            ((float*)(sm + O_PI))[t] = g_P[base + i0 + t];
            ((float*)(sm + O_UI))[t] = g_U[base + i0 + t];
        } else {
            int u = t - 64;
            ((float*)(sm + O_PJ))[u] = g_P[base + j0 + u];
            ((float*)(sm + O_UJ))[u] = g_U[base + j0 + u];
        }
    }
    __syncthreads();

    int wm = wid >> 1;          // 0..1  (m block of 32)
    int wn = wid & 1;           // 0..1  (n block of 32)

    float acc[2][4][4];
#pragma unroll
    for (int mt = 0; mt < 2; mt++)
#pragma unroll
        for (int nt = 0; nt < 4; nt++)
#pragma unroll
            for (int r = 0; r < 4; r++) acc[mt][nt][r] = 0.0f;

    int lm = lane >> 3, lr = lane & 7;
    // A x4: lanes 0-7 rows+0 k0 / 8-15 rows+8 k0 / 16-23 rows+0 k16B / 24-31 rows+8 k16B
    int a_row = wm * 32 + (lm & 1) * 8 + lr;
    int a_kb  = (lm >> 1) * 16;
    // B x4 (covers 2 nt): lanes 0-7 ntA k0 / 8-15 ntA k16B / 16-23 ntB k0 / 24-31 ntB k16B
    int b_row = wn * 32 + ((lane >> 4) & 1) * 8 + lr;
    int b_kb  = ((lane >> 3) & 1) * 16;

    const int passA[3] = {T_AH, T_AH, T_AL};
    const int passB[3] = {T_BH, T_BL, T_BH};

#pragma unroll
    for (int p = 0; p < 3; p++) {
        uint32_t aBase = sb + passA[p] + a_row * LDB + a_kb;
        uint32_t bBase = sb + passB[p] + b_row * LDB + b_kb;
#pragma unroll
        for (int ks = 0; ks < 4; ks++) {
            uint32_t a[2][4], bf[4][2];
#pragma unroll
            for (int mt = 0; mt < 2; mt++)
                ldsm_x4(a[mt][0], a[mt][1], a[mt][2], a[mt][3],
                        aBase + mt * 16 * LDB + ks * 32);
#pragma unroll
            for (int pr = 0; pr < 2; pr++)
                ldsm_x4(bf[pr * 2][0], bf[pr * 2][1],
                        bf[pr * 2 + 1][0], bf[pr * 2 + 1][1],
                        bBase + pr * 16 * LDB + ks * 32);
#pragma unroll
            for (int mt = 0; mt < 2; mt++)
#pragma unroll
                for (int nt = 0; nt < 4; nt++)
                    mma16816(acc[mt][nt], a[mt], bf[nt]);
        }
    }

    // All ldsm reads done; staging may overwrite the tile region.
    __syncthreads();

    // ---- epilogue ----
    float sc = scale_p[0];
    float nscln2 = -sc * 0.6931471805599453f;
    int g  = lane >> 2;          // 0..7
    int tq = lane & 3;           // 0..3
    const float* sPi = (const float*)(sm + O_PI);
    const float* sUi = (const float*)(sm + O_UI);
    const float* sPj = (const float*)(sm + O_PJ);
    const float* sUj = (const float*)(sm + O_UJ);
    float* stag = (float*)sm;    // [j][i], pitch PSTAG floats (overlays tiles)

#pragma unroll
    for (int mt = 0; mt < 2; mt++) {
        int i_a = wm * 32 + mt * 16 + g;
        int i_b = i_a + 8;
        float Pia = sPi[i_a], Uia = sUi[i_a];
        float Pib = sPi[i_b], Uib = sUi[i_b];
        size_t rowA = (size_t)b * S * S + (size_t)(i0 + i_a) * S + j0;
        size_t rowB = rowA + 8u * S;
#pragma unroll
        for (int nt = 0; nt < 4; nt++) {
            int j_c = wn * 32 + nt * 8 + 2 * tq;
            float Pj0 = sPj[j_c],     Uj0 = sUj[j_c];
            float Pj1 = sPj[j_c + 1], Uj1 = sUj[j_c + 1];
            float2 oA, oB;
            oA.x = bias_elt(Pia, Uia, Pj0, Uj0, acc[mt][nt][0], nscln2);
            oA.y = bias_elt(Pia, Uia, Pj1, Uj1, acc[mt][nt][1], nscln2);
            oB.x = bias_elt(Pib, Uib, Pj0, Uj0, acc[mt][nt][2], nscln2);
            oB.y = bias_elt(Pib, Uib, Pj1, Uj1, acc[mt][nt][3], nscln2);
            *(float2*)(out + rowA + j_c) = oA;
            *(float2*)(out + rowB + j_c) = oB;
            if (mirror) {
                // transposed staging (STS banks 8*tq+g: conflict-free)
                stag[(j_c)     * PSTAG + i_a] = oA.x;
                stag[(j_c + 1) * PSTAG + i_a] = oA.y;
                stag[(j_c)     * PSTAG + i_b] = oB.x;
                stag[(j_c + 1) * PSTAG + i_b] = oB.y;
            }
        }
    }

    // ---- mirror: coalesced store of the transposed tile at (j0, i0) ----
    if (mirror) {
        __syncthreads();
        size_t mbase = (size_t)b * S * S + (size_t)j0 * S + i0;
#pragma unroll
        for (int r = 0; r < 8; r++) {
            int idx2 = r * 128 + t;             // 0..1023
            int j = idx2 >> 4, c = idx2 & 15;   // 64 rows x 16 float4-chunks
            float4 v = *(const float4*)(stag + j * PSTAG + 4 * c);
            *(float4*)(out + mbase + (size_t)j * S + 4 * c) = v;
        }
    }
}

// ---------------------------------------------------------------------------
extern "C" void kernel_launch(void* const* d_in, const int* in_sizes, int n_in,
                              void* d_out, int out_size) {
    const void*  ids     = d_in[0];
    const float* W       = (const float*)d_in[1];
    const float* scale_p = (const float*)d_in[2];
    float* out = (float*)d_out;

    int n_ids   = in_sizes[0];            // B*S = 4096
    int num_tok = in_sizes[1] / D;        // 30522
    int S       = out_size / n_ids;       // 1024
    int B       = n_ids / S;              // 4

    int prep_blocks = (n_ids + 7) / 8;
    prep_kernel<<<prep_blocks, 256>>>(ids, W, n_ids, num_tok);

    static int attr_set = 0;
    if (!attr_set) {
        cudaFuncSetAttribute(bias_kernel,
                             cudaFuncAttributeMaxDynamicSharedMemorySize,
                             SMEM_TOT);
        attr_set = 1;
    }

    int ntile = S / 64;
    int pairs = ntile * (ntile + 1) / 2;  // 136 for S=1024
    dim3 grid(pairs, 1, B);
    bias_kernel<<<grid, 256 / 2, SMEM_TOT>>>(scale_p, out, S);
}